// round 14
// baseline (speedup 1.0000x reference)
#include <cuda_runtime.h>
#include <math_constants.h>

#define CCH   512
#define HH    64
#define WW    64
#define FX    7
#define FY    7
#define BINS  (FX*FY)            // 49
#define SEG   (CCH*BINS)         // 25088
#define DTOT  (SEG*6)            // 150528
#define NOUT  1024
#define KCHUNK 256
#define NCHUNKS (DTOT/KCHUNK)    // 588
#define CPSEG (SEG/KCHUNK)       // 98 chunks per segment
#define MAXSPAN 10               // max rows/cols per adaptive bin for 64-size dim
#define PGRP  8                  // pools per block (2 blocks per channel)
#define RPARTS 32                // reduce: K-part slices per block
#define RCPP  19                 // ceil(588/32) chunks per part

// Scratch (no allocation allowed in kernel_launch)
__device__ float g_pools[16 * SEG];              // 16 pools, each [C, FX, FY] channel-major
__device__ float g_partial[NCHUNKS * 3 * NOUT];  // 7.2 MB

// ---------------------------------------------------------------------------
// Pool kernel: grid (nch, 2), 256 threads; channel = chbase + blockIdx.x.
// Each block computes 8 pools x 49 bins for its channel via separable 2-pass
// max with precomputed bound tables and fixed-trip idempotent-clamped loops.
// Pool index map: 0 = scene, 1..3 = human[i], 4..15 = obj-union(i,j) (i*4+j).
// ---------------------------------------------------------------------------
__global__ void __launch_bounds__(256) pool_kernel(
    const float* __restrict__ feature,
    const float* __restrict__ pbox,   // [3,4] x1,y1,x2,y2 (image coords)
    const float* __restrict__ obox,   // [4,4]
    const float* __restrict__ ratio,  // [2]
    int chbase)
{
    __shared__ float2 plane2[HH * WW / 2];        // 16 KB  [r][xpair]
    __shared__ float  strip[PGRP * FX * WW];      // 14 KB  [pl*FX+i][x]
    __shared__ int by0[PGRP], by1[PGRP], bxx0[PGRP], bxx1[PGRP];
    __shared__ int srs[PGRP * FX], sre[PGRP * FX];   // row-bin bounds per (pl,i)
    __shared__ int scs[PGRP * FY], sce[PGRP * FY];   // col-bin bounds per (pl,j)

    const int ch    = chbase + blockIdx.x;
    const int pbase = blockIdx.y * PGRP;
    const int tid   = threadIdx.x;

    if (tid < PGRP) {
        const float rx = ratio[0], ry = ratio[1];
        int p = pbase + tid;
        int x0, y0, x1, y1;
        if (p == 0) {
            x0 = 0; y0 = 0; x1 = WW; y1 = HH;
        } else if (p < 4) {
            int i = p - 1;
            x0 = (int)rintf(pbox[i*4+0] * rx);
            y0 = (int)rintf(pbox[i*4+1] * ry);
            x1 = (int)rintf(pbox[i*4+2] * rx);
            y1 = (int)rintf(pbox[i*4+3] * ry);
        } else {
            int q = p - 4; int i = q >> 2; int j = q & 3;
            int px0 = (int)rintf(pbox[i*4+0] * rx);
            int py0 = (int)rintf(pbox[i*4+1] * ry);
            int px1 = (int)rintf(pbox[i*4+2] * rx);
            int py1 = (int)rintf(pbox[i*4+3] * ry);
            int ox0 = (int)rintf(obox[j*4+0] * rx);
            int oy0 = (int)rintf(obox[j*4+1] * ry);
            int ox1 = (int)rintf(obox[j*4+2] * rx);
            int oy1 = (int)rintf(obox[j*4+3] * ry);
            x0 = min(px0, ox0); y0 = min(py0, oy0);
            x1 = max(px1, ox1); y1 = max(py1, oy1);
        }
        bxx0[tid] = x0; by0[tid] = y0; bxx1[tid] = x1; by1[tid] = y1;
    }
    __syncthreads();

    // Bin-bound tables (divisions by 7 happen once, outside hot loops).
    if (tid < PGRP * FX) {
        int pl = tid / FX, i = tid - pl * FX;
        int y0 = by0[pl], h = by1[pl] - y0;
        srs[tid] = y0 + (i * h) / FX;
        sre[tid] = y0 + ((i + 1) * h + FX - 1) / FX;
    } else if (tid >= 64 && tid < 64 + PGRP * FY) {
        int t = tid - 64;
        int pl = t / FY, j = t - pl * FY;
        int x0 = bxx0[pl], w = bxx1[pl] - x0;
        scs[t] = x0 + (j * w) / FY;
        sce[t] = x0 + ((j + 1) * w + FY - 1) / FY;
    }

    // Coalesced plane load (1024 float4 over 256 threads = 4 each)
    {
        const float4* src = (const float4*)(feature + (size_t)ch * (HH * WW));
        float4* dst = (float4*)plane2;
        dst[tid]       = src[tid];
        dst[tid + 256] = src[tid + 256];
        dst[tid + 512] = src[tid + 512];
        dst[tid + 768] = src[tid + 768];
    }
    __syncthreads();

    // Pass 1: 56 strips over 8 warps = 7 serial strips/warp.
    // Lane = column pair (float2), conflict-free. Unroll 10, clamped-idempotent.
    {
        const int warp = tid >> 5;
        const int lane = tid & 31;
        #pragma unroll
        for (int s = 0; s < 7; s++) {
            const int t  = warp + s * 8;
            const int rs = srs[t];
            const int rl = sre[t] - 1;          // last valid row of this bin
            float2 m = make_float2(-CUDART_INF_F, -CUDART_INF_F);
            #pragma unroll
            for (int k = 0; k < MAXSPAN; k++) {
                int r = min(rs + k, rl);        // idempotent re-max when past end
                float2 v = plane2[r * (WW / 2) + lane];
                m.x = fmaxf(m.x, v.x);
                m.y = fmaxf(m.y, v.y);
            }
            strip[t * WW + 2 * lane]     = m.x;
            strip[t * WW + 2 * lane + 1] = m.y;
        }
    }
    __syncthreads();

    // Pass 2: 392 bins over 256 threads (<=2 each). Unroll 10, clamped-idempotent.
    #pragma unroll
    for (int pass = 0; pass < 2; pass++) {
        int t = tid + pass * 256;
        if (t < PGRP * BINS) {
            int pl  = t / BINS;
            int bin = t - pl * BINS;
            int i = bin / FY, j = bin - i * FY;
            int cs = scs[pl * FY + j];
            int cl = sce[pl * FY + j] - 1;      // last valid col of this bin
            const float* s = strip + (pl * FX + i) * WW;
            float m = -CUDART_INF_F;
            #pragma unroll
            for (int k = 0; k < MAXSPAN; k++) {
                int c = min(cs + k, cl);
                m = fmaxf(m, s[c]);
            }
            g_pools[(pbase + pl) * SEG + ch * BINS + bin] = m;
        }
    }
}

// ---------------------------------------------------------------------------
// Split-K GEMM half: 294 blocks, block b -> segment b/49, chunk index
// ibase + b%49 within the segment. Chunks with index <= 48 touch only
// channels 0..255; index >= 49 only channels 249..511 (needs all of poolB's
// 256..511 plus poolA overlap) -> gemmA depends on poolA only, gemmB on both.
// ---------------------------------------------------------------------------
__global__ void __launch_bounds__(256, 4) gemm_kernel(const float* __restrict__ Wf,
                                                      int ibase)
{
    __shared__ float sa0[KCHUNK], sa1[KCHUNK], sa2[KCHUNK];

    const int b      = blockIdx.x;          // 0..293
    const int seg    = b / 49;              // 0..5
    const int idx    = ibase + b - seg * 49;
    const int chunk  = seg * CPSEG + idx;
    const int k0     = chunk * KCHUNK;
    const int within = idx * KCHUNK;

    int p0, p1, p2;
    if (seg == 0)      { p0 = 1;       p1 = 2;       p2 = 3;       } // human[m]
    else if (seg == 5) { p0 = 0;       p1 = 0;       p2 = 0;       } // scene
    else               { p0 = 3 + seg; p1 = 7 + seg; p2 = 11 + seg; } // obj[4m+seg-1]

    const int tid = threadIdx.x;
    sa0[tid] = g_pools[p0 * SEG + within + tid];
    sa1[tid] = g_pools[p1 * SEG + within + tid];
    sa2[tid] = g_pools[p2 * SEG + within + tid];
    __syncthreads();

    const int n = tid * 4;
    const float* wp = Wf + (size_t)k0 * NOUT + n;

    float4 s0 = make_float4(0.f, 0.f, 0.f, 0.f);
    float4 s1 = s0, s2 = s0;

    for (int d = 0; d < KCHUNK; d += 8) {
        float4 w[8];
        #pragma unroll
        for (int u = 0; u < 8; u++)
            w[u] = __ldcs((const float4*)(wp + (size_t)u * NOUT));
        wp += 8 * NOUT;
        #pragma unroll
        for (int u = 0; u < 8; u++) {
            float x0 = sa0[d + u];
            float x1 = sa1[d + u];
            float x2 = sa2[d + u];
            s0.x = fmaf(x0, w[u].x, s0.x); s0.y = fmaf(x0, w[u].y, s0.y);
            s0.z = fmaf(x0, w[u].z, s0.z); s0.w = fmaf(x0, w[u].w, s0.w);
            s1.x = fmaf(x1, w[u].x, s1.x); s1.y = fmaf(x1, w[u].y, s1.y);
            s1.z = fmaf(x1, w[u].z, s1.z); s1.w = fmaf(x1, w[u].w, s1.w);
            s2.x = fmaf(x2, w[u].x, s2.x); s2.y = fmaf(x2, w[u].y, s2.y);
            s2.z = fmaf(x2, w[u].z, s2.z); s2.w = fmaf(x2, w[u].w, s2.w);
        }
    }

    float* outp = g_partial + (size_t)chunk * 3 * NOUT;
    *(float4*)(outp + n)            = s0;
    *(float4*)(outp + NOUT + n)     = s1;
    *(float4*)(outp + 2 * NOUT + n) = s2;
}

// ---------------------------------------------------------------------------
// Deterministic reduce + bias. 96 blocks x 1024 threads.
// Block covers 32 outputs (lane) x 32 K-part slices (<=19 chunks each),
// then SMEM tree over parts.
// ---------------------------------------------------------------------------
__global__ void __launch_bounds__(1024) reduce_kernel(
    const float* __restrict__ bias, float* __restrict__ out)
{
    __shared__ float red[RPARTS * 32];
    const int tid  = threadIdx.x;
    const int lane = tid & 31;
    const int part = tid >> 5;                       // 0..31
    const int i    = blockIdx.x * 32 + lane;         // output index 0..3071

    const int cbeg = part * RCPP;
    const int cend = min(NCHUNKS, cbeg + RCPP);

    float s = 0.f;
    const float* src = g_partial + (size_t)cbeg * (3 * NOUT) + i;
    #pragma unroll
    for (int k = 0; k < RCPP; k++) {
        if (cbeg + k < cend)
            s += src[(size_t)k * (3 * NOUT)];
    }

    red[part * 32 + lane] = s;
    __syncthreads();

    #pragma unroll
    for (int st = RPARTS / 2; st > 0; st >>= 1) {
        if (part < st)
            red[part * 32 + lane] += red[(part + st) * 32 + lane];
        __syncthreads();
    }

    if (part == 0)
        out[i] = red[lane] + bias[i & (NOUT - 1)];
}

extern "C" void kernel_launch(void* const* d_in, const int* in_sizes, int n_in,
                              void* d_out, int out_size)
{
    const float* feature = (const float*)d_in[0];
    const float* pbox    = (const float*)d_in[1];
    const float* obox    = (const float*)d_in[2];
    const float* ratio   = (const float*)d_in[3];
    const float* Wf      = (const float*)d_in[4];
    const float* bias    = (const float*)d_in[5];
    float* out = (float*)d_out;

    // One-time side streams/events for the capture fork (created lazily; the
    // GPU work enqueued is identical on every call).
    static cudaStream_t s1 = nullptr, s2 = nullptr;
    static cudaEvent_t evA = nullptr, evB = nullptr, evGA = nullptr, evGB = nullptr;
    if (s1 == nullptr) {
        cudaStreamCreateWithFlags(&s1, cudaStreamNonBlocking);
        cudaStreamCreateWithFlags(&s2, cudaStreamNonBlocking);
        cudaEventCreateWithFlags(&evA,  cudaEventDisableTiming);
        cudaEventCreateWithFlags(&evB,  cudaEventDisableTiming);
        cudaEventCreateWithFlags(&evGA, cudaEventDisableTiming);
        cudaEventCreateWithFlags(&evGB, cudaEventDisableTiming);
    }

    // poolA (ch 0..255) -> evA ; poolB (ch 256..511) -> evB   [default stream]
    dim3 pgrid(CCH / 2, 2);
    pool_kernel<<<pgrid, 256>>>(feature, pbox, obox, ratio, 0);
    cudaEventRecord(evA, 0);
    pool_kernel<<<pgrid, 256>>>(feature, pbox, obox, ratio, CCH / 2);
    cudaEventRecord(evB, 0);

    // gemmA needs only poolA's channels; runs concurrently with poolB.
    cudaStreamWaitEvent(s1, evA, 0);
    gemm_kernel<<<294, 256, 0, s1>>>(Wf, 0);
    cudaEventRecord(evGA, s1);

    cudaStreamWaitEvent(s2, evB, 0);
    gemm_kernel<<<294, 256, 0, s2>>>(Wf, 49);
    cudaEventRecord(evGB, s2);

    // Join both gemm halves back into the captured stream, then reduce.
    cudaStreamWaitEvent(0, evGA, 0);
    cudaStreamWaitEvent(0, evGB, 0);
    reduce_kernel<<<96, 1024>>>(bias, out);
}

// round 15
// speedup vs baseline: 1.1787x; 1.1787x over previous
#include <cuda_runtime.h>
#include <math_constants.h>

#define CCH   512
#define HH    64
#define WW    64
#define FX    7
#define FY    7
#define BINS  (FX*FY)            // 49
#define SEG   (CCH*BINS)         // 25088
#define DTOT  (SEG*6)            // 150528
#define NOUT  1024
#define KCHUNK 256
#define NCHUNKS (DTOT/KCHUNK)    // 588
#define MAXSPAN 10               // max rows/cols per adaptive bin for 64-size dim
#define PGRP  4                  // pools per block (4 blocks per channel)
#define RPARTS 32                // reduce: K-part slices per block
#define RCPP  19                 // ceil(588/32) chunks per part

// Scratch (no allocation allowed in kernel_launch)
__device__ float g_pools[16 * SEG];              // 16 pools, each [C, FX, FY] channel-major
__device__ float g_partial[NCHUNKS * 3 * NOUT];  // 7.2 MB

// ---------------------------------------------------------------------------
// Pool kernel: grid (512 channels, 4 pool-groups), 256 threads. Pass 1 reads
// the feature plane DIRECTLY from global (coalesced float2 per lane; the 16KB
// plane lives in L1 and is reused across strips and across the channel's
// co-resident y-blocks) -> no SMEM staging phase, ~8KB smem, 8 blocks/SM.
// Separable 2-pass max; bounds precomputed; hot loops fixed-trip (10) with
// index clamped to the bin's last valid element (idempotent re-max).
// Pool index map: 0 = scene, 1..3 = human[i], 4..15 = obj-union(i,j) (i*4+j).
// ---------------------------------------------------------------------------
__global__ void __launch_bounds__(256) pool_kernel(
    const float* __restrict__ feature,
    const float* __restrict__ pbox,   // [3,4] x1,y1,x2,y2 (image coords)
    const float* __restrict__ obox,   // [4,4]
    const float* __restrict__ ratio)  // [2]
{
    __shared__ float strip[PGRP * FX * WW];          // 7 KB  [pl*FX+i][x]
    __shared__ int by0[PGRP], by1[PGRP], bxx0[PGRP], bxx1[PGRP];
    __shared__ int srs[PGRP * FX], sre[PGRP * FX];   // row-bin bounds per (pl,i)
    __shared__ int scs[PGRP * FY], sce[PGRP * FY];   // col-bin bounds per (pl,j)

    const int ch    = blockIdx.x;
    const int pbase = blockIdx.y * PGRP;
    const int tid   = threadIdx.x;

    if (tid < PGRP) {
        const float rx = ratio[0], ry = ratio[1];
        int p = pbase + tid;
        int x0, y0, x1, y1;
        if (p == 0) {
            x0 = 0; y0 = 0; x1 = WW; y1 = HH;
        } else if (p < 4) {
            int i = p - 1;
            x0 = (int)rintf(pbox[i*4+0] * rx);
            y0 = (int)rintf(pbox[i*4+1] * ry);
            x1 = (int)rintf(pbox[i*4+2] * rx);
            y1 = (int)rintf(pbox[i*4+3] * ry);
        } else {
            int q = p - 4; int i = q >> 2; int j = q & 3;
            int px0 = (int)rintf(pbox[i*4+0] * rx);
            int py0 = (int)rintf(pbox[i*4+1] * ry);
            int px1 = (int)rintf(pbox[i*4+2] * rx);
            int py1 = (int)rintf(pbox[i*4+3] * ry);
            int ox0 = (int)rintf(obox[j*4+0] * rx);
            int oy0 = (int)rintf(obox[j*4+1] * ry);
            int ox1 = (int)rintf(obox[j*4+2] * rx);
            int oy1 = (int)rintf(obox[j*4+3] * ry);
            x0 = min(px0, ox0); y0 = min(py0, oy0);
            x1 = max(px1, ox1); y1 = max(py1, oy1);
        }
        bxx0[tid] = x0; by0[tid] = y0; bxx1[tid] = x1; by1[tid] = y1;
    }
    __syncthreads();

    // Bin-bound tables (divisions by 7 happen once, outside hot loops).
    if (tid < PGRP * FX) {
        int pl = tid / FX, i = tid - pl * FX;
        int y0 = by0[pl], h = by1[pl] - y0;
        srs[tid] = y0 + (i * h) / FX;
        sre[tid] = y0 + ((i + 1) * h + FX - 1) / FX;
    } else if (tid >= 64 && tid < 64 + PGRP * FY) {
        int t = tid - 64;
        int pl = t / FY, j = t - pl * FY;
        int x0 = bxx0[pl], w = bxx1[pl] - x0;
        scs[t] = x0 + (j * w) / FY;
        sce[t] = x0 + ((j + 1) * w + FY - 1) / FY;
    }
    __syncthreads();

    // Pass 1: 28 strips over 8 warps (<=4 serial strips/warp). Lane = column
    // pair; reads go straight to global (L1-resident after first touch).
    {
        const int warp = tid >> 5;
        const int lane = tid & 31;
        const float2* fp = (const float2*)(feature + (size_t)ch * (HH * WW));
        #pragma unroll
        for (int s = 0; s < 4; s++) {
            const int t = warp + s * 8;
            if (t < PGRP * FX) {
                const int rs = srs[t];
                const int rl = sre[t] - 1;      // last valid row of this bin
                float2 m = make_float2(-CUDART_INF_F, -CUDART_INF_F);
                #pragma unroll
                for (int k = 0; k < MAXSPAN; k++) {
                    int r = min(rs + k, rl);    // idempotent re-max when past end
                    float2 v = __ldg(fp + r * (WW / 2) + lane);
                    m.x = fmaxf(m.x, v.x);
                    m.y = fmaxf(m.y, v.y);
                }
                strip[t * WW + 2 * lane]     = m.x;
                strip[t * WW + 2 * lane + 1] = m.y;
            }
        }
    }
    __syncthreads();

    // Pass 2: 196 bins over 256 threads (1 each). Unroll 10, clamped-idempotent.
    if (tid < PGRP * BINS) {
        int pl  = tid / BINS;
        int bin = tid - pl * BINS;
        int i = bin / FY, j = bin - i * FY;
        int cs = scs[pl * FY + j];
        int cl = sce[pl * FY + j] - 1;          // last valid col of this bin
        const float* s = strip + (pl * FX + i) * WW;
        float m = -CUDART_INF_F;
        #pragma unroll
        for (int k = 0; k < MAXSPAN; k++) {
            int c = min(cs + k, cl);
            m = fmaxf(m, s[c]);
        }
        g_pools[(pbase + pl) * SEG + ch * BINS + bin] = m;
    }
}

// ---------------------------------------------------------------------------
// Split-K GEMM: out[m,n] = sum_d act[m,d] * W[d,n]
// act row m = concat(human[m], obj[4m..4m+3], scene); each 256-row K-chunk
// lies entirely in one concat segment (256 divides 25088), so activations
// are 3 base pointers into g_pools, staged in SMEM.
// One block = all 1024 N columns (256 thr x float4), one K-chunk of 256.
// ---------------------------------------------------------------------------
__global__ void __launch_bounds__(256, 4) gemm_kernel(const float* __restrict__ Wf)
{
    __shared__ float sa0[KCHUNK], sa1[KCHUNK], sa2[KCHUNK];

    const int chunk  = blockIdx.x;
    const int k0     = chunk * KCHUNK;
    const int seg    = k0 / SEG;            // 0..5
    const int within = k0 - seg * SEG;

    int p0, p1, p2;
    if (seg == 0)      { p0 = 1;       p1 = 2;       p2 = 3;       } // human[m]
    else if (seg == 5) { p0 = 0;       p1 = 0;       p2 = 0;       } // scene
    else               { p0 = 3 + seg; p1 = 7 + seg; p2 = 11 + seg; } // obj[4m+seg-1]

    const int tid = threadIdx.x;
    sa0[tid] = g_pools[p0 * SEG + within + tid];
    sa1[tid] = g_pools[p1 * SEG + within + tid];
    sa2[tid] = g_pools[p2 * SEG + within + tid];
    __syncthreads();

    const int n = tid * 4;
    const float* wp = Wf + (size_t)k0 * NOUT + n;

    float4 s0 = make_float4(0.f, 0.f, 0.f, 0.f);
    float4 s1 = s0, s2 = s0;

    for (int d = 0; d < KCHUNK; d += 8) {
        float4 w[8];
        #pragma unroll
        for (int u = 0; u < 8; u++)
            w[u] = __ldcs((const float4*)(wp + (size_t)u * NOUT));
        wp += 8 * NOUT;
        #pragma unroll
        for (int u = 0; u < 8; u++) {
            float x0 = sa0[d + u];
            float x1 = sa1[d + u];
            float x2 = sa2[d + u];
            s0.x = fmaf(x0, w[u].x, s0.x); s0.y = fmaf(x0, w[u].y, s0.y);
            s0.z = fmaf(x0, w[u].z, s0.z); s0.w = fmaf(x0, w[u].w, s0.w);
            s1.x = fmaf(x1, w[u].x, s1.x); s1.y = fmaf(x1, w[u].y, s1.y);
            s1.z = fmaf(x1, w[u].z, s1.z); s1.w = fmaf(x1, w[u].w, s1.w);
            s2.x = fmaf(x2, w[u].x, s2.x); s2.y = fmaf(x2, w[u].y, s2.y);
            s2.z = fmaf(x2, w[u].z, s2.z); s2.w = fmaf(x2, w[u].w, s2.w);
        }
    }

    float* outp = g_partial + (size_t)chunk * 3 * NOUT;
    *(float4*)(outp + n)            = s0;
    *(float4*)(outp + NOUT + n)     = s1;
    *(float4*)(outp + 2 * NOUT + n) = s2;
}

// ---------------------------------------------------------------------------
// Deterministic reduce + bias. 96 blocks x 1024 threads.
// Block covers 32 outputs (lane, coalesced) x 32 K-part slices (<=19 chunks
// each), then SMEM tree over parts.
// ---------------------------------------------------------------------------
__global__ void __launch_bounds__(1024) reduce_kernel(
    const float* __restrict__ bias, float* __restrict__ out)
{
    __shared__ float red[RPARTS * 32];
    const int tid  = threadIdx.x;
    const int lane = tid & 31;
    const int part = tid >> 5;                       // 0..31
    const int i    = blockIdx.x * 32 + lane;         // output index 0..3071

    const int cbeg = part * RCPP;
    const int cend = min(NCHUNKS, cbeg + RCPP);

    float s = 0.f;
    const float* src = g_partial + (size_t)cbeg * (3 * NOUT) + i;
    #pragma unroll
    for (int k = 0; k < RCPP; k++) {
        if (cbeg + k < cend)
            s += src[(size_t)k * (3 * NOUT)];
    }

    red[part * 32 + lane] = s;
    __syncthreads();

    #pragma unroll
    for (int st = RPARTS / 2; st > 0; st >>= 1) {
        if (part < st)
            red[part * 32 + lane] += red[(part + st) * 32 + lane];
        __syncthreads();
    }

    if (part == 0)
        out[i] = red[lane] + bias[i & (NOUT - 1)];
}

extern "C" void kernel_launch(void* const* d_in, const int* in_sizes, int n_in,
                              void* d_out, int out_size)
{
    const float* feature = (const float*)d_in[0];
    const float* pbox    = (const float*)d_in[1];
    const float* obox    = (const float*)d_in[2];
    const float* ratio   = (const float*)d_in[3];
    const float* Wf      = (const float*)d_in[4];
    const float* bias    = (const float*)d_in[5];
    float* out = (float*)d_out;

    dim3 pgrid(CCH, 4);
    pool_kernel<<<pgrid, 256>>>(feature, pbox, obox, ratio);
    gemm_kernel<<<NCHUNKS, 256>>>(Wf);
    reduce_kernel<<<96, 1024>>>(bias, out);
}

// round 16
// speedup vs baseline: 1.2320x; 1.0453x over previous
#include <cuda_runtime.h>
#include <math_constants.h>

#define CCH   512
#define HH    64
#define WW    64
#define FX    7
#define FY    7
#define BINS  (FX*FY)            // 49
#define SEG   (CCH*BINS)         // 25088
#define DTOT  (SEG*6)            // 150528
#define NOUT  1024
#define KCHUNK 256
#define NCHUNKS (DTOT/KCHUNK)    // 588
#define MAXSPAN 10               // max rows/cols per adaptive bin for 64-size dim
#define PGRP  4                  // pools per block (4 blocks per channel)
#define RPARTS 32                // reduce: K-part slices per block
#define RCPP  19                 // ceil(588/32) chunks per part
#define PF_LPC 1024              // prefetch lines (128B) per chunk = 128 KB
#define PF_PER_BLK 294           // 588*1024 / 2048 pool blocks

// Scratch (no allocation allowed in kernel_launch)
__device__ float g_pools[16 * SEG];              // 16 pools, each [C, FX, FY] channel-major
__device__ float g_partial[NCHUNKS * 3 * NOUT];  // 7.2 MB

// ---------------------------------------------------------------------------
// Pool kernel: grid (512 channels, 4 pool-groups), 256 threads.
// PROLOGUE: each block issues ~294 fire-and-forget L2 prefetches covering the
// first 128 KB of every GEMM K-chunk of W (77 MB total) — this streams W into
// the (launch-persistent) L2 during pool's otherwise idle DRAM window, so the
// following GEMM's first reads are L2 hits.
// BODY: separable 2-pass adaptive max; pass 1 reads the feature plane directly
// from global (coalesced float2, L1-resident); bounds precomputed to SMEM
// tables; hot loops fixed-trip (10) with index clamped to the bin's last valid
// element (idempotent re-max -> no predicates).
// Pool index map: 0 = scene, 1..3 = human[i], 4..15 = obj-union(i,j) (i*4+j).
// ---------------------------------------------------------------------------
__global__ void __launch_bounds__(256) pool_kernel(
    const float* __restrict__ feature,
    const float* __restrict__ pbox,   // [3,4] x1,y1,x2,y2 (image coords)
    const float* __restrict__ obox,   // [4,4]
    const float* __restrict__ ratio,  // [2]
    const float* __restrict__ Wf)     // for L2 prefetch only
{
    __shared__ float strip[PGRP * FX * WW];          // 7 KB  [pl*FX+i][x]
    __shared__ int by0[PGRP], by1[PGRP], bxx0[PGRP], bxx1[PGRP];
    __shared__ int srs[PGRP * FX], sre[PGRP * FX];   // row-bin bounds per (pl,i)
    __shared__ int scs[PGRP * FY], sce[PGRP * FY];   // col-bin bounds per (pl,j)

    const int ch    = blockIdx.x;
    const int pbase = blockIdx.y * PGRP;
    const int tid   = threadIdx.x;

    // ---- W L2-prefetch prologue (no dependencies, fire-and-forget) ----
    {
        const int bidlin = blockIdx.y * gridDim.x + blockIdx.x;   // 0..2047
        const int lbase  = bidlin * PF_PER_BLK;
        #pragma unroll
        for (int u = 0; u < 2; u++) {
            int o = tid + u * 256;
            if (o < PF_PER_BLK) {
                int l   = lbase + o;
                int c   = l >> 10;                 // chunk (PF_LPC = 1024)
                int off = l & (PF_LPC - 1);
                const char* p = (const char*)Wf
                              + (size_t)c * (KCHUNK * NOUT * 4)
                              + (size_t)off * 128;
                asm volatile("prefetch.global.L2 [%0];" :: "l"(p));
            }
        }
    }

    if (tid < PGRP) {
        const float rx = ratio[0], ry = ratio[1];
        int p = pbase + tid;
        int x0, y0, x1, y1;
        if (p == 0) {
            x0 = 0; y0 = 0; x1 = WW; y1 = HH;
        } else if (p < 4) {
            int i = p - 1;
            x0 = (int)rintf(pbox[i*4+0] * rx);
            y0 = (int)rintf(pbox[i*4+1] * ry);
            x1 = (int)rintf(pbox[i*4+2] * rx);
            y1 = (int)rintf(pbox[i*4+3] * ry);
        } else {
            int q = p - 4; int i = q >> 2; int j = q & 3;
            int px0 = (int)rintf(pbox[i*4+0] * rx);
            int py0 = (int)rintf(pbox[i*4+1] * ry);
            int px1 = (int)rintf(pbox[i*4+2] * rx);
            int py1 = (int)rintf(pbox[i*4+3] * ry);
            int ox0 = (int)rintf(obox[j*4+0] * rx);
            int oy0 = (int)rintf(obox[j*4+1] * ry);
            int ox1 = (int)rintf(obox[j*4+2] * rx);
            int oy1 = (int)rintf(obox[j*4+3] * ry);
            x0 = min(px0, ox0); y0 = min(py0, oy0);
            x1 = max(px1, ox1); y1 = max(py1, oy1);
        }
        bxx0[tid] = x0; by0[tid] = y0; bxx1[tid] = x1; by1[tid] = y1;
    }
    __syncthreads();

    // Bin-bound tables (divisions by 7 happen once, outside hot loops).
    if (tid < PGRP * FX) {
        int pl = tid / FX, i = tid - pl * FX;
        int y0 = by0[pl], h = by1[pl] - y0;
        srs[tid] = y0 + (i * h) / FX;
        sre[tid] = y0 + ((i + 1) * h + FX - 1) / FX;
    } else if (tid >= 64 && tid < 64 + PGRP * FY) {
        int t = tid - 64;
        int pl = t / FY, j = t - pl * FY;
        int x0 = bxx0[pl], w = bxx1[pl] - x0;
        scs[t] = x0 + (j * w) / FY;
        sce[t] = x0 + ((j + 1) * w + FY - 1) / FY;
    }
    __syncthreads();

    // Pass 1: 28 strips over 8 warps (<=4 serial strips/warp). Lane = column
    // pair; reads go straight to global (L1-resident after first touch).
    {
        const int warp = tid >> 5;
        const int lane = tid & 31;
        const float2* fp = (const float2*)(feature + (size_t)ch * (HH * WW));
        #pragma unroll
        for (int s = 0; s < 4; s++) {
            const int t = warp + s * 8;
            if (t < PGRP * FX) {
                const int rs = srs[t];
                const int rl = sre[t] - 1;      // last valid row of this bin
                float2 m = make_float2(-CUDART_INF_F, -CUDART_INF_F);
                #pragma unroll
                for (int k = 0; k < MAXSPAN; k++) {
                    int r = min(rs + k, rl);    // idempotent re-max when past end
                    float2 v = __ldg(fp + r * (WW / 2) + lane);
                    m.x = fmaxf(m.x, v.x);
                    m.y = fmaxf(m.y, v.y);
                }
                strip[t * WW + 2 * lane]     = m.x;
                strip[t * WW + 2 * lane + 1] = m.y;
            }
        }
    }
    __syncthreads();

    // Pass 2: 196 bins over 256 threads (1 each). Unroll 10, clamped-idempotent.
    if (tid < PGRP * BINS) {
        int pl  = tid / BINS;
        int bin = tid - pl * BINS;
        int i = bin / FY, j = bin - i * FY;
        int cs = scs[pl * FY + j];
        int cl = sce[pl * FY + j] - 1;          // last valid col of this bin
        const float* s = strip + (pl * FX + i) * WW;
        float m = -CUDART_INF_F;
        #pragma unroll
        for (int k = 0; k < MAXSPAN; k++) {
            int c = min(cs + k, cl);
            m = fmaxf(m, s[c]);
        }
        g_pools[(pbase + pl) * SEG + ch * BINS + bin] = m;
    }
}

// ---------------------------------------------------------------------------
// Split-K GEMM: out[m,n] = sum_d act[m,d] * W[d,n]
// act row m = concat(human[m], obj[4m..4m+3], scene); each 256-row K-chunk
// lies entirely in one concat segment (256 divides 25088), so activations
// are 3 base pointers into g_pools, staged in SMEM.
// One block = all 1024 N columns (256 thr x float4), one K-chunk of 256.
// The first 128 KB of each chunk was L2-prefetched by pool_kernel.
// ---------------------------------------------------------------------------
__global__ void __launch_bounds__(256, 4) gemm_kernel(const float* __restrict__ Wf)
{
    __shared__ float sa0[KCHUNK], sa1[KCHUNK], sa2[KCHUNK];

    const int chunk  = blockIdx.x;
    const int k0     = chunk * KCHUNK;
    const int seg    = k0 / SEG;            // 0..5
    const int within = k0 - seg * SEG;

    int p0, p1, p2;
    if (seg == 0)      { p0 = 1;       p1 = 2;       p2 = 3;       } // human[m]
    else if (seg == 5) { p0 = 0;       p1 = 0;       p2 = 0;       } // scene
    else               { p0 = 3 + seg; p1 = 7 + seg; p2 = 11 + seg; } // obj[4m+seg-1]

    const int tid = threadIdx.x;
    sa0[tid] = g_pools[p0 * SEG + within + tid];
    sa1[tid] = g_pools[p1 * SEG + within + tid];
    sa2[tid] = g_pools[p2 * SEG + within + tid];
    __syncthreads();

    const int n = tid * 4;
    const float* wp = Wf + (size_t)k0 * NOUT + n;

    float4 s0 = make_float4(0.f, 0.f, 0.f, 0.f);
    float4 s1 = s0, s2 = s0;

    for (int d = 0; d < KCHUNK; d += 8) {
        float4 w[8];
        #pragma unroll
        for (int u = 0; u < 8; u++)
            w[u] = __ldcs((const float4*)(wp + (size_t)u * NOUT));
        wp += 8 * NOUT;
        #pragma unroll
        for (int u = 0; u < 8; u++) {
            float x0 = sa0[d + u];
            float x1 = sa1[d + u];
            float x2 = sa2[d + u];
            s0.x = fmaf(x0, w[u].x, s0.x); s0.y = fmaf(x0, w[u].y, s0.y);
            s0.z = fmaf(x0, w[u].z, s0.z); s0.w = fmaf(x0, w[u].w, s0.w);
            s1.x = fmaf(x1, w[u].x, s1.x); s1.y = fmaf(x1, w[u].y, s1.y);
            s1.z = fmaf(x1, w[u].z, s1.z); s1.w = fmaf(x1, w[u].w, s1.w);
            s2.x = fmaf(x2, w[u].x, s2.x); s2.y = fmaf(x2, w[u].y, s2.y);
            s2.z = fmaf(x2, w[u].z, s2.z); s2.w = fmaf(x2, w[u].w, s2.w);
        }
    }

    float* outp = g_partial + (size_t)chunk * 3 * NOUT;
    *(float4*)(outp + n)            = s0;
    *(float4*)(outp + NOUT + n)     = s1;
    *(float4*)(outp + 2 * NOUT + n) = s2;
}

// ---------------------------------------------------------------------------
// Deterministic reduce + bias. 96 blocks x 1024 threads.
// Block covers 32 outputs (lane, coalesced) x 32 K-part slices (<=19 chunks
// each), then SMEM tree over parts.
// ---------------------------------------------------------------------------
__global__ void __launch_bounds__(1024) reduce_kernel(
    const float* __restrict__ bias, float* __restrict__ out)
{
    __shared__ float red[RPARTS * 32];
    const int tid  = threadIdx.x;
    const int lane = tid & 31;
    const int part = tid >> 5;                       // 0..31
    const int i    = blockIdx.x * 32 + lane;         // output index 0..3071

    const int cbeg = part * RCPP;
    const int cend = min(NCHUNKS, cbeg + RCPP);

    float s = 0.f;
    const float* src = g_partial + (size_t)cbeg * (3 * NOUT) + i;
    #pragma unroll
    for (int k = 0; k < RCPP; k++) {
        if (cbeg + k < cend)
            s += src[(size_t)k * (3 * NOUT)];
    }

    red[part * 32 + lane] = s;
    __syncthreads();

    #pragma unroll
    for (int st = RPARTS / 2; st > 0; st >>= 1) {
        if (part < st)
            red[part * 32 + lane] += red[(part + st) * 32 + lane];
        __syncthreads();
    }

    if (part == 0)
        out[i] = red[lane] + bias[i & (NOUT - 1)];
}

extern "C" void kernel_launch(void* const* d_in, const int* in_sizes, int n_in,
                              void* d_out, int out_size)
{
    const float* feature = (const float*)d_in[0];
    const float* pbox    = (const float*)d_in[1];
    const float* obox    = (const float*)d_in[2];
    const float* ratio   = (const float*)d_in[3];
    const float* Wf      = (const float*)d_in[4];
    const float* bias    = (const float*)d_in[5];
    float* out = (float*)d_out;

    dim3 pgrid(CCH, 4);
    pool_kernel<<<pgrid, 256>>>(feature, pbox, obox, ratio, Wf);
    gemm_kernel<<<NCHUNKS, 256>>>(Wf);
    reduce_kernel<<<96, 1024>>>(bias, out);
}